// round 8
// baseline (speedup 1.0000x reference)
#include <cuda_runtime.h>
#include <cuda_fp16.h>
#include <math_constants.h>

#define BB 4
#define QL 1024
#define KLEN 1024
#define CC 256
#define HH 8
#define DD 32
#define MM (BB * QL)

// Scratch device globals (no allocation allowed)
__device__ __half g_xq [MM * CC];      // fp16(q_x)
__device__ __half g_xkv[MM * CC];      // fp16(kv_x)
__device__ __half g_wts[5 * CC * CC];  // fp16(wq,wk,wv,wg,wo)
__device__ __half g_qp[MM * CC];       // fp16(q * log2e / sqrt(D))
__device__ __half g_kp[MM * CC];       // fp16(k)
__device__ __half g_vt[MM * CC];       // fp16(v) TRANSPOSED: [(b*H+h)*D+d][tok]
__device__ float  g_gp[MM * CC];       // sigmoid gate (fp32)
__device__ __half g_o [MM * CC];       // fp16(gated attention out)

__device__ __forceinline__ unsigned packh2(float lo, float hi) {
    __half2 h = __floats2half2_rn(lo, hi);
    return *reinterpret_cast<unsigned*>(&h);
}
__device__ __forceinline__ float ex2f(float x) {
    float d;
    asm("ex2.approx.f32 %0, %1;" : "=f"(d) : "f"(x));
    return d;
}

__device__ __forceinline__ void mma_f16(float c[4],
                                        unsigned a0, unsigned a1, unsigned a2, unsigned a3,
                                        unsigned b0, unsigned b1) {
    asm volatile(
        "mma.sync.aligned.m16n8k16.row.col.f32.f16.f16.f32 "
        "{%0,%1,%2,%3}, {%4,%5,%6,%7}, {%8,%9}, {%0,%1,%2,%3};"
        : "+f"(c[0]), "+f"(c[1]), "+f"(c[2]), "+f"(c[3])
        : "r"(a0), "r"(a1), "r"(a2), "r"(a3), "r"(b0), "r"(b1));
}

__device__ __forceinline__ void cp16(void* dst_smem, const void* src) {
    unsigned d = (unsigned)__cvta_generic_to_shared(dst_smem);
    asm volatile("cp.async.cg.shared.global [%0], [%1], 16;" :: "r"(d), "l"(src));
}
#define CP_COMMIT() asm volatile("cp.async.commit_group;")
#define CP_WAIT0()  asm volatile("cp.async.wait_group 0;")

// ---------------------------------------------------------------------------
// Prep: fp16-convert q_x, kv_x, five weight matrices. Grid (1024,3) x 256.
// ---------------------------------------------------------------------------
__global__ __launch_bounds__(256)
void prep_f16(const float* __restrict__ qx, const float* __restrict__ kvx,
              const float* __restrict__ wq, const float* __restrict__ wk,
              const float* __restrict__ wv, const float* __restrict__ wg,
              const float* __restrict__ wo)
{
    const int seg = blockIdx.y;
    const int i4 = blockIdx.x * 256 + threadIdx.x;
    const float* src; __half* dst; int idx = i4;
    if (seg == 0)      { src = qx;  dst = g_xq;  }
    else if (seg == 1) { src = kvx; dst = g_xkv; }
    else {
        if (i4 >= 5 * CC * CC / 4) return;
        int w = i4 / (CC * CC / 4);
        idx = i4 - w * (CC * CC / 4);
        const float* ws[5] = {wq, wk, wv, wg, wo};
        src = ws[w];
        dst = g_wts + (size_t)w * CC * CC;
    }
    float4 v = ((const float4*)src)[idx];
    uint2 u;
    u.x = packh2(v.x, v.y);
    u.y = packh2(v.z, v.w);
    ((uint2*)dst)[idx] = u;
}

// ---------------------------------------------------------------------------
// fp16 GEMM v3: single-stage full-K tiles, no intra-loop syncs.
// Y[m][n] = sum_k X[m][k]*W[n][k]; BM=64 BN=64 K=256; 256 thr (2m x 4n warps).
// smem: A[64][264]h + B[64][264]h = 67584 B.
// modes: 0 q(*log2e/sqrtD) 1 k 2 v(transposed out) 3 gate 4 out.
// ---------------------------------------------------------------------------
#define G_ROW 264
#define GEMM_SMEM (2 * 64 * G_ROW * 2)

__global__ __launch_bounds__(256, 3)
void gemm_f16(const float* __restrict__ bg, const float* __restrict__ bo,
              float* __restrict__ outp, int mode_base)
{
    extern __shared__ __half smh[];
    __half* As = smh;                  // [64][264]
    __half* Bs = smh + 64 * G_ROW;     // [64][264]

    const int mode = mode_base + blockIdx.z;
    const __half* X; const __half* W; const float* bias = nullptr;
    switch (mode) {
        case 0:  X = g_xq;  W = g_wts;               break;
        case 1:  X = g_xkv; W = g_wts + 1 * CC * CC; break;
        case 2:  X = g_xkv; W = g_wts + 2 * CC * CC; break;
        case 3:  X = g_xq;  W = g_wts + 3 * CC * CC; bias = bg; break;
        default: X = g_o;   W = g_wts + 4 * CC * CC; bias = bo; break;
    }

    const int tid  = threadIdx.x;
    const int lane = tid & 31;
    const int warp = tid >> 5;
    const int wm = warp & 1;
    const int wn = warp >> 1;
    const int g = lane >> 2, tig = lane & 3;
    const int m0 = blockIdx.x * 64;
    const int n0 = blockIdx.y * 64;

    // Load full 64x256 A and B tiles (one commit, one wait, one sync)
    #pragma unroll
    for (int p = 0; p < 8; p++) {
        int ch = tid + p * 256;           // 2048 chunks: 64 rows x 32 chunks
        int r = ch >> 5, c = (ch & 31) * 8;
        cp16(As + r * G_ROW + c, X + (size_t)(m0 + r) * CC + c);
        cp16(Bs + r * G_ROW + c, W + (size_t)(n0 + r) * CC + c);
    }
    CP_COMMIT();
    CP_WAIT0();
    __syncthreads();

    float acc[2][2][4] = {};

    #pragma unroll
    for (int kst = 0; kst < 16; kst++) {
        unsigned a[2][4];
        #pragma unroll
        for (int mt = 0; mt < 2; mt++) {
            int row = wm * 32 + mt * 16;
            a[mt][0] = *(const unsigned*)(As + (row + g    ) * G_ROW + kst * 16 + 2 * tig);
            a[mt][1] = *(const unsigned*)(As + (row + g + 8) * G_ROW + kst * 16 + 2 * tig);
            a[mt][2] = *(const unsigned*)(As + (row + g    ) * G_ROW + kst * 16 + 2 * tig + 8);
            a[mt][3] = *(const unsigned*)(As + (row + g + 8) * G_ROW + kst * 16 + 2 * tig + 8);
        }
        #pragma unroll
        for (int nt = 0; nt < 2; nt++) {
            int n = wn * 16 + nt * 8;
            unsigned b0 = *(const unsigned*)(Bs + (n + g) * G_ROW + kst * 16 + 2 * tig);
            unsigned b1 = *(const unsigned*)(Bs + (n + g) * G_ROW + kst * 16 + 2 * tig + 8);
            mma_f16(acc[0][nt], a[0][0], a[0][1], a[0][2], a[0][3], b0, b1);
            mma_f16(acc[1][nt], a[1][0], a[1][1], a[1][2], a[1][3], b0, b1);
        }
    }

    // Epilogue
    #pragma unroll
    for (int mt = 0; mt < 2; mt++) {
        int row0 = m0 + wm * 32 + mt * 16 + g;
        #pragma unroll
        for (int nt = 0; nt < 2; nt++) {
            int col = n0 + wn * 16 + nt * 8 + 2 * tig;
            float v[4] = {acc[mt][nt][0], acc[mt][nt][1], acc[mt][nt][2], acc[mt][nt][3]};
            if (mode == 0) {
                const float QS = 1.4426950408889634f / 5.656854249492381f;
                #pragma unroll
                for (int u = 0; u < 4; u++) v[u] *= QS;
            } else if (mode == 3) {
                float b0v = bias[col], b1v = bias[col + 1];
                v[0] = 1.0f / (1.0f + __expf(-(v[0] + b0v)));
                v[1] = 1.0f / (1.0f + __expf(-(v[1] + b1v)));
                v[2] = 1.0f / (1.0f + __expf(-(v[2] + b0v)));
                v[3] = 1.0f / (1.0f + __expf(-(v[3] + b1v)));
            } else if (mode == 4) {
                float b0v = bias[col], b1v = bias[col + 1];
                v[0] += b0v; v[1] += b1v; v[2] += b0v; v[3] += b1v;
            }
            if (mode == 2) {
                int bidx = row0 >> 10, tok = row0 & 1023;
                int hh = col >> 5, dd = col & 31;
                size_t base = ((size_t)(bidx * HH + hh) * DD + dd) * KLEN + tok;
                g_vt[base]            = __float2half_rn(v[0]);
                g_vt[base + KLEN]     = __float2half_rn(v[1]);
                g_vt[base + 8]        = __float2half_rn(v[2]);
                g_vt[base + KLEN + 8] = __float2half_rn(v[3]);
            } else if (mode == 0 || mode == 1) {
                __half* Y = (mode == 0) ? g_qp : g_kp;
                *(__half2*)(Y + (size_t)row0 * CC + col)       = __floats2half2_rn(v[0], v[1]);
                *(__half2*)(Y + (size_t)(row0 + 8) * CC + col) = __floats2half2_rn(v[2], v[3]);
            } else if (mode == 3) {
                *(float2*)(g_gp + (size_t)row0 * CC + col)       = make_float2(v[0], v[1]);
                *(float2*)(g_gp + (size_t)(row0 + 8) * CC + col) = make_float2(v[2], v[3]);
            } else {
                *(float2*)(outp + (size_t)row0 * CC + col)       = make_float2(v[0], v[1]);
                *(float2*)(outp + (size_t)(row0 + 8) * CC + col) = make_float2(v[2], v[3]);
            }
        }
    }
}

// ---------------------------------------------------------------------------
// Fused flash attention + gating v4: key-split 8 warps, pair_bias via direct
// coalesced LDG (no smem staging) -> smem 28.7 KB -> 4+ CTAs/SM.
// No-max softmax (q pre-scaled by log2e), ex2.approx.f32, clamp 15.
// Grid (Q/64, H, B), 256 threads.
// ---------------------------------------------------------------------------
#define AT_KS   0
#define AT_VT   10240
#define AT_QS   19456
#define AT_MSK  24576
#define ATT_SMEM 28672

__global__ __launch_bounds__(256, 4)
void attn_f16(const float* __restrict__ mask_bias,
              const float* __restrict__ pair_bias)
{
    extern __shared__ char smc[];
    __half* ks  = (__half*)(smc + AT_KS);    // [2][64][40]
    __half* vt  = (__half*)(smc + AT_VT);    // [2][32][72]
    __half* qs  = (__half*)(smc + AT_QS);    // [64][40]
    float*  msk = (float*)(smc + AT_MSK);    // [1024]

    const int tid  = threadIdx.x;
    const int lane = tid & 31;
    const int warp = tid >> 5;
    const int g = lane >> 2, tig = lane & 3;
    const int q0 = blockIdx.x * 64;
    const int h  = blockIdx.y;
    const int b  = blockIdx.z;
    const int wr   = (warp & 3) * 16;    // query-row offset
    const int koff = (warp >> 2) * 32;   // key offset within tile
    const float L2E = 1.4426950408889634f;

    auto loadKV = [&](int st, int kt) {
        {   // K: 64x32h = 256 chunks, 1/thread
            int r = tid >> 2, c = (tid & 3) * 8;
            cp16(ks + (st * 64 + r) * 40 + c,
                 g_kp + (size_t)(b * KLEN + kt * 64 + r) * CC + h * DD + c);
        }
        {   // Vt: 32x64h = 256 chunks, 1/thread
            int r = tid >> 3, c = (tid & 7) * 8;
            cp16(vt + (st * 32 + r) * 72 + c,
                 g_vt + ((size_t)(b * HH + h) * DD + r) * KLEN + kt * 64 + c);
        }
    };

    // Prologue: Q + mask + tile 0
    {
        int r = tid >> 2, c = (tid & 3) * 8;
        cp16(qs + r * 40 + c, g_qp + (size_t)(b * QL + q0 + r) * CC + h * DD + c);
    }
    cp16(msk + tid * 4, mask_bias + (size_t)b * KLEN + tid * 4);
    loadKV(0, 0);
    CP_COMMIT();
    CP_WAIT0();
    __syncthreads();

    unsigned aq[2][4];
    #pragma unroll
    for (int kst = 0; kst < 2; kst++) {
        aq[kst][0] = *(const unsigned*)(qs + (wr + g    ) * 40 + kst * 16 + 2 * tig);
        aq[kst][1] = *(const unsigned*)(qs + (wr + g + 8) * 40 + kst * 16 + 2 * tig);
        aq[kst][2] = *(const unsigned*)(qs + (wr + g    ) * 40 + kst * 16 + 2 * tig + 8);
        aq[kst][3] = *(const unsigned*)(qs + (wr + g + 8) * 40 + kst * 16 + 2 * tig + 8);
    }

    // Base pointer for this thread's pair_bias rows (advanced by 64 per tile)
    const float* pbA = pair_bias
        + ((size_t)((b * HH + h) * QL + q0 + wr + g)) * KLEN + koff + 2 * tig;

    float o[4][4] = {};        // partial over this warp's key half
    float l0 = 0.0f, l1 = 0.0f;

    for (int kt = 0; kt < 16; kt++) {
        const int k0 = kt * 64;
        const int cur = kt & 1;

        if (kt < 15) {
            loadKV(cur ^ 1, kt + 1);
            CP_COMMIT();
        }

        // hoisted bias LDGs (consumed after QK mma)
        float2 p0[4], p1[4];
        const float* pb = pbA + k0;
        #pragma unroll
        for (int nt = 0; nt < 4; nt++) {
            p0[nt] = *(const float2*)(pb + nt * 8);
            p1[nt] = *(const float2*)(pb + 8 * (size_t)KLEN + nt * 8);
        }

        // QK^T over 32 keys (4 n-tiles)
        const __half* kb = ks + cur * 64 * 40;
        float s[4][4] = {};
        #pragma unroll
        for (int kst = 0; kst < 2; kst++) {
            #pragma unroll
            for (int nt = 0; nt < 4; nt++) {
                int krow = koff + nt * 8 + g;
                unsigned b0 = *(const unsigned*)(kb + krow * 40 + kst * 16 + 2 * tig);
                unsigned b1 = *(const unsigned*)(kb + krow * 40 + kst * 16 + 2 * tig + 8);
                mma_f16(s[nt], aq[kst][0], aq[kst][1], aq[kst][2], aq[kst][3], b0, b1);
            }
        }

        // bias (x log2e), clamp, exp2, sum, pack to fp16
        unsigned ph[4][2];
        float rs0 = 0.0f, rs1 = 0.0f;
        #pragma unroll
        for (int nt = 0; nt < 4; nt++) {
            int col = koff + nt * 8 + 2 * tig;
            float2 mk = *(const float2*)(msk + k0 + col);
            float e0 = ex2f(fminf(fmaf(p0[nt].x + mk.x, L2E, s[nt][0]), 15.0f));
            float e1 = ex2f(fminf(fmaf(p0[nt].y + mk.y, L2E, s[nt][1]), 15.0f));
            float e2 = ex2f(fminf(fmaf(p1[nt].x + mk.x, L2E, s[nt][2]), 15.0f));
            float e3 = ex2f(fminf(fmaf(p1[nt].y + mk.y, L2E, s[nt][3]), 15.0f));
            rs0 += e0 + e1;
            rs1 += e2 + e3;
            ph[nt][0] = packh2(e0, e1);
            ph[nt][1] = packh2(e2, e3);
        }
        rs0 += __shfl_xor_sync(0xffffffffu, rs0, 1);
        rs0 += __shfl_xor_sync(0xffffffffu, rs0, 2);
        rs1 += __shfl_xor_sync(0xffffffffu, rs1, 1);
        rs1 += __shfl_xor_sync(0xffffffffu, rs1, 2);
        l0 += rs0;
        l1 += rs1;

        // AV over 32 keys (2 k-steps)
        const __half* vb = vt + cur * 32 * 72;
        #pragma unroll
        for (int kst = 0; kst < 2; kst++) {
            unsigned a0 = ph[2 * kst    ][0];
            unsigned a1 = ph[2 * kst    ][1];
            unsigned a2 = ph[2 * kst + 1][0];
            unsigned a3 = ph[2 * kst + 1][1];
            #pragma unroll
            for (int nt = 0; nt < 4; nt++) {
                unsigned b0 = *(const unsigned*)(vb + (nt * 8 + g) * 72 + koff + kst * 16 + 2 * tig);
                unsigned b1 = *(const unsigned*)(vb + (nt * 8 + g) * 72 + koff + kst * 16 + 2 * tig + 8);
                mma_f16(o[nt], a0, a1, a2, a3, b0, b1);
            }
        }

        if (kt < 15) { CP_WAIT0(); }
        __syncthreads();
    }

    // Cross-warp reduction: warps 4-7 publish partials into reused K smem,
    // warps 0-3 combine + gate + store.
    float* osm = (float*)(smc + AT_KS);   // [64][34]
    float* lsm = osm + 64 * 34;           // [64]
    if (warp >= 4) {
        #pragma unroll
        for (int nt = 0; nt < 4; nt++) {
            int col = nt * 8 + 2 * tig;
            *(float2*)&osm[(wr + g    ) * 34 + col] = make_float2(o[nt][0], o[nt][1]);
            *(float2*)&osm[(wr + g + 8) * 34 + col] = make_float2(o[nt][2], o[nt][3]);
        }
        if (tig == 0) {
            lsm[wr + g]     = l0;
            lsm[wr + g + 8] = l1;
        }
    }
    __syncthreads();
    if (warp < 4) {
        float invl0 = 1.0f / (l0 + lsm[wr + g]);
        float invl1 = 1.0f / (l1 + lsm[wr + g + 8]);
        #pragma unroll
        for (int nt = 0; nt < 4; nt++) {
            int col = nt * 8 + 2 * tig;
            float2 q0v = *(const float2*)&osm[(wr + g    ) * 34 + col];
            float2 q1v = *(const float2*)&osm[(wr + g + 8) * 34 + col];
            float v0 = o[nt][0] + q0v.x, v1 = o[nt][1] + q0v.y;
            float v2 = o[nt][2] + q1v.x, v3 = o[nt][3] + q1v.y;
            size_t base0 = (size_t)(b * QL + q0 + wr + g) * CC + h * DD + col;
            size_t base1 = base0 + 8 * (size_t)CC;
            float2 ga = *(const float2*)(g_gp + base0);
            float2 gb = *(const float2*)(g_gp + base1);
            *(__half2*)(g_o + base0) = __floats2half2_rn(v0 * invl0 * ga.x,
                                                         v1 * invl0 * ga.y);
            *(__half2*)(g_o + base1) = __floats2half2_rn(v2 * invl1 * gb.x,
                                                         v3 * invl1 * gb.y);
        }
    }
}

// ---------------------------------------------------------------------------
extern "C" void kernel_launch(void* const* d_in, const int* in_sizes, int n_in,
                              void* d_out, int out_size)
{
    (void)in_sizes; (void)n_in; (void)out_size;
    const float* q_x       = (const float*)d_in[0];
    const float* kv_x      = (const float*)d_in[1];
    const float* mask_bias = (const float*)d_in[2];
    const float* pair_bias = (const float*)d_in[3];
    const float* wq        = (const float*)d_in[4];
    const float* wk        = (const float*)d_in[5];
    const float* wv        = (const float*)d_in[6];
    const float* wg        = (const float*)d_in[7];
    const float* bg        = (const float*)d_in[8];
    const float* wo        = (const float*)d_in[9];
    const float* bo        = (const float*)d_in[10];
    float* out = (float*)d_out;

    static bool attr_done = false;
    if (!attr_done) {
        cudaFuncSetAttribute(gemm_f16, cudaFuncAttributeMaxDynamicSharedMemorySize, GEMM_SMEM);
        cudaFuncSetAttribute(attn_f16, cudaFuncAttributeMaxDynamicSharedMemorySize, ATT_SMEM);
        attr_done = true;
    }

    prep_f16<<<dim3(1024, 3), 256>>>(q_x, kv_x, wq, wk, wv, wg, wo);

    gemm_f16<<<dim3(MM / 64, CC / 64, 4), 256, GEMM_SMEM>>>(bg, bo, nullptr, 0);

    attn_f16<<<dim3(QL / 64, HH, BB), 256, ATT_SMEM>>>(mask_bias, pair_bias);

    gemm_f16<<<dim3(MM / 64, CC / 64, 1), 256, GEMM_SMEM>>>(bg, bo, out, 4);
}

// round 10
// speedup vs baseline: 1.0602x; 1.0602x over previous
#include <cuda_runtime.h>
#include <cuda_fp16.h>
#include <math_constants.h>

#define BB 4
#define QL 1024
#define KLEN 1024
#define CC 256
#define HH 8
#define DD 32
#define MM (BB * QL)

// Scratch device globals (no allocation allowed)
__device__ __half g_xq [MM * CC];      // fp16(q_x)
__device__ __half g_xkv[MM * CC];      // fp16(kv_x)
__device__ __half g_wts[5 * CC * CC];  // fp16(wq,wk,wv,wg,wo)
__device__ __half g_qp[MM * CC];       // fp16(q * log2e / sqrt(D))
__device__ __half g_kp[MM * CC];       // fp16(k)
__device__ __half g_vt[MM * CC];       // fp16(v) TRANSPOSED: [(b*H+h)*D+d][tok]
__device__ float  g_gp[MM * CC];       // sigmoid gate (fp32)
__device__ __half g_o [MM * CC];       // fp16(gated attention out)

__device__ __forceinline__ unsigned packh2(float lo, float hi) {
    __half2 h = __floats2half2_rn(lo, hi);
    return *reinterpret_cast<unsigned*>(&h);
}
__device__ __forceinline__ unsigned ex2h2(unsigned x) {
    unsigned d;
    asm("ex2.approx.f16x2 %0, %1;" : "=r"(d) : "r"(x));
    return d;
}
__device__ __forceinline__ unsigned hmin2c(unsigned a, unsigned b) {
    unsigned d;
    asm("min.f16x2 %0, %1, %2;" : "=r"(d) : "r"(a), "r"(b));
    return d;
}

__device__ __forceinline__ void mma_f16(float c[4],
                                        unsigned a0, unsigned a1, unsigned a2, unsigned a3,
                                        unsigned b0, unsigned b1) {
    asm volatile(
        "mma.sync.aligned.m16n8k16.row.col.f32.f16.f16.f32 "
        "{%0,%1,%2,%3}, {%4,%5,%6,%7}, {%8,%9}, {%0,%1,%2,%3};"
        : "+f"(c[0]), "+f"(c[1]), "+f"(c[2]), "+f"(c[3])
        : "r"(a0), "r"(a1), "r"(a2), "r"(a3), "r"(b0), "r"(b1));
}

__device__ __forceinline__ void cp16(void* dst_smem, const void* src) {
    unsigned d = (unsigned)__cvta_generic_to_shared(dst_smem);
    asm volatile("cp.async.cg.shared.global [%0], [%1], 16;" :: "r"(d), "l"(src));
}
#define CP_COMMIT() asm volatile("cp.async.commit_group;")
#define CP_WAIT0()  asm volatile("cp.async.wait_group 0;")
#define CP_WAIT1()  asm volatile("cp.async.wait_group 1;")
#define CP_WAIT2()  asm volatile("cp.async.wait_group 2;")

// ---------------------------------------------------------------------------
// Prep: fp16-convert q_x, kv_x, five weight matrices. Grid (1024,3) x 256.
// ---------------------------------------------------------------------------
__global__ __launch_bounds__(256)
void prep_f16(const float* __restrict__ qx, const float* __restrict__ kvx,
              const float* __restrict__ wq, const float* __restrict__ wk,
              const float* __restrict__ wv, const float* __restrict__ wg,
              const float* __restrict__ wo)
{
    const int seg = blockIdx.y;
    const int i4 = blockIdx.x * 256 + threadIdx.x;
    const float* src; __half* dst; int idx = i4;
    if (seg == 0)      { src = qx;  dst = g_xq;  }
    else if (seg == 1) { src = kvx; dst = g_xkv; }
    else {
        if (i4 >= 5 * CC * CC / 4) return;
        int w = i4 / (CC * CC / 4);
        idx = i4 - w * (CC * CC / 4);
        const float* ws[5] = {wq, wk, wv, wg, wo};
        src = ws[w];
        dst = g_wts + (size_t)w * CC * CC;
    }
    float4 v = ((const float4*)src)[idx];
    uint2 u;
    u.x = packh2(v.x, v.y);
    u.y = packh2(v.z, v.w);
    ((uint2*)dst)[idx] = u;
}

// ---------------------------------------------------------------------------
// fp16 GEMM (R5/R7 proven config): Y[m][n]=sum_k X[m][k]*W[n][k].
// BM=64 BN=64 BK=32; 256 thr (2m x 4n warps). 3-stage cp.async pipeline.
// modes: 0 q(*log2e/sqrtD) 1 k 2 v(transposed out) 3 gate 4 out.
// ---------------------------------------------------------------------------
#define G_STAGE (64 * 40)
#define GEMM_SMEM (3 * 2 * G_STAGE * 2)         // 30720 B

__global__ __launch_bounds__(256)
void gemm_f16(const float* __restrict__ bg, const float* __restrict__ bo,
              float* __restrict__ outp, int mode_base)
{
    extern __shared__ __half smh[];
    __half* As = smh;                  // [3][64][40]
    __half* Bs = smh + 3 * G_STAGE;    // [3][64][40]

    const int mode = mode_base + blockIdx.z;
    const __half* X; const __half* W; const float* bias = nullptr;
    switch (mode) {
        case 0:  X = g_xq;  W = g_wts;               break;
        case 1:  X = g_xkv; W = g_wts + 1 * CC * CC; break;
        case 2:  X = g_xkv; W = g_wts + 2 * CC * CC; break;
        case 3:  X = g_xq;  W = g_wts + 3 * CC * CC; bias = bg; break;
        default: X = g_o;   W = g_wts + 4 * CC * CC; bias = bo; break;
    }

    const int tid  = threadIdx.x;
    const int lane = tid & 31;
    const int warp = tid >> 5;
    const int wm = warp & 1;
    const int wn = warp >> 1;
    const int g = lane >> 2, tig = lane & 3;
    const int m0 = blockIdx.x * 64;
    const int n0 = blockIdx.y * 64;

    const int r = tid >> 2;            // 0..63
    const int c = (tid & 3) * 8;       // 0..24

    auto loadTiles = [&](int st, int kk) {
        cp16(As + (st * 64 + r) * 40 + c, X + (size_t)(m0 + r) * CC + kk + c);
        cp16(Bs + (st * 64 + r) * 40 + c, W + (size_t)(n0 + r) * CC + kk + c);
    };

    float acc[2][2][4] = {};

    loadTiles(0, 0);  CP_COMMIT();
    loadTiles(1, 32); CP_COMMIT();

    for (int kt = 0; kt < 8; kt++) {
        const int st = kt % 3;
        if (kt + 2 < 8) {
            loadTiles((kt + 2) % 3, (kt + 2) * 32);
            CP_COMMIT();
            CP_WAIT2();
        } else if (kt == 6) {
            CP_WAIT1();
        } else {
            CP_WAIT0();
        }
        __syncthreads();

        const __half* Ab = As + st * G_STAGE;
        const __half* Bb = Bs + st * G_STAGE;
        #pragma unroll
        for (int kst = 0; kst < 2; kst++) {
            unsigned a[2][4];
            #pragma unroll
            for (int mt = 0; mt < 2; mt++) {
                int row = wm * 32 + mt * 16;
                a[mt][0] = *(const unsigned*)(Ab + (row + g    ) * 40 + kst * 16 + 2 * tig);
                a[mt][1] = *(const unsigned*)(Ab + (row + g + 8) * 40 + kst * 16 + 2 * tig);
                a[mt][2] = *(const unsigned*)(Ab + (row + g    ) * 40 + kst * 16 + 2 * tig + 8);
                a[mt][3] = *(const unsigned*)(Ab + (row + g + 8) * 40 + kst * 16 + 2 * tig + 8);
            }
            #pragma unroll
            for (int nt = 0; nt < 2; nt++) {
                int n = wn * 16 + nt * 8;
                unsigned b0 = *(const unsigned*)(Bb + (n + g) * 40 + kst * 16 + 2 * tig);
                unsigned b1 = *(const unsigned*)(Bb + (n + g) * 40 + kst * 16 + 2 * tig + 8);
                mma_f16(acc[0][nt], a[0][0], a[0][1], a[0][2], a[0][3], b0, b1);
                mma_f16(acc[1][nt], a[1][0], a[1][1], a[1][2], a[1][3], b0, b1);
            }
        }
        __syncthreads();
    }

    // Epilogue
    #pragma unroll
    for (int mt = 0; mt < 2; mt++) {
        int row0 = m0 + wm * 32 + mt * 16 + g;
        #pragma unroll
        for (int nt = 0; nt < 2; nt++) {
            int col = n0 + wn * 16 + nt * 8 + 2 * tig;
            float v[4] = {acc[mt][nt][0], acc[mt][nt][1], acc[mt][nt][2], acc[mt][nt][3]};
            if (mode == 0) {
                const float QS = 1.4426950408889634f / 5.656854249492381f;
                #pragma unroll
                for (int u = 0; u < 4; u++) v[u] *= QS;
            } else if (mode == 3) {
                float b0v = bias[col], b1v = bias[col + 1];
                v[0] = 1.0f / (1.0f + __expf(-(v[0] + b0v)));
                v[1] = 1.0f / (1.0f + __expf(-(v[1] + b1v)));
                v[2] = 1.0f / (1.0f + __expf(-(v[2] + b0v)));
                v[3] = 1.0f / (1.0f + __expf(-(v[3] + b1v)));
            } else if (mode == 4) {
                float b0v = bias[col], b1v = bias[col + 1];
                v[0] += b0v; v[1] += b1v; v[2] += b0v; v[3] += b1v;
            }
            if (mode == 2) {
                int bidx = row0 >> 10, tok = row0 & 1023;
                int hh = col >> 5, dd = col & 31;
                size_t base = ((size_t)(bidx * HH + hh) * DD + dd) * KLEN + tok;
                g_vt[base]            = __float2half_rn(v[0]);
                g_vt[base + KLEN]     = __float2half_rn(v[1]);
                g_vt[base + 8]        = __float2half_rn(v[2]);
                g_vt[base + KLEN + 8] = __float2half_rn(v[3]);
            } else if (mode == 0 || mode == 1) {
                __half* Y = (mode == 0) ? g_qp : g_kp;
                *(__half2*)(Y + (size_t)row0 * CC + col)       = __floats2half2_rn(v[0], v[1]);
                *(__half2*)(Y + (size_t)(row0 + 8) * CC + col) = __floats2half2_rn(v[2], v[3]);
            } else if (mode == 3) {
                *(float2*)(g_gp + (size_t)row0 * CC + col)       = make_float2(v[0], v[1]);
                *(float2*)(g_gp + (size_t)(row0 + 8) * CC + col) = make_float2(v[2], v[3]);
            } else {
                *(float2*)(outp + (size_t)row0 * CC + col)       = make_float2(v[0], v[1]);
                *(float2*)(outp + (size_t)(row0 + 8) * CC + col) = make_float2(v[2], v[3]);
            }
        }
    }
}

// ---------------------------------------------------------------------------
// Fused flash attention + gating v5 (R7 skeleton):
// key-split 8 warps, bias via cp.async smem, 2-stage K/V.
// NEW: f16x2 exp (halves MUFU) + row-sum via ones-column mma (no per-tile
// reductions/shuffles). fp32 bias FMA preserved (R6-validated numerics).
// Grid (Q/64, H, B), 256 threads.
// ---------------------------------------------------------------------------
#define AT_KS   0
#define AT_VT   10240
#define AT_BS   19456
#define AT_QS   58368
#define AT_MSK  63488
#define ATT_SMEM 67584

__global__ __launch_bounds__(256)
void attn_f16(const float* __restrict__ mask_bias,
              const float* __restrict__ pair_bias)
{
    extern __shared__ char smc[];
    __half* ks  = (__half*)(smc + AT_KS);    // [2][64][40]
    __half* vt  = (__half*)(smc + AT_VT);    // [2][32][72]
    float*  bsm = (float*)(smc + AT_BS);     // [2][64][76] (reused for reduction)
    __half* qs  = (__half*)(smc + AT_QS);    // [64][40]
    float*  msk = (float*)(smc + AT_MSK);    // [1024]

    const int tid  = threadIdx.x;
    const int lane = tid & 31;
    const int warp = tid >> 5;
    const int g = lane >> 2, tig = lane & 3;
    const int q0 = blockIdx.x * 64;
    const int h  = blockIdx.y;
    const int b  = blockIdx.z;
    const int wr   = (warp & 3) * 16;    // query-row offset
    const int koff = (warp >> 2) * 32;   // key offset within tile
    const float L2E = 1.4426950408889634f;
    const unsigned bone = (lane < 4) ? 0x3C003C00u : 0u;  // ones column (n=0)
    const unsigned CLMP = 0x4BF84BF8u;                    // (15.9375, 15.9375)

    auto loadKVB = [&](int st, int kt) {
        {   // K: 64x32h = 256 chunks, 1/thread
            int r = tid >> 2, c = (tid & 3) * 8;
            cp16(ks + (st * 64 + r) * 40 + c,
                 g_kp + (size_t)(b * KLEN + kt * 64 + r) * CC + h * DD + c);
        }
        {   // Vt: 32x64h = 256 chunks, 1/thread
            int r = tid >> 3, c = (tid & 7) * 8;
            cp16(vt + (st * 32 + r) * 72 + c,
                 g_vt + ((size_t)(b * HH + h) * DD + r) * KLEN + kt * 64 + c);
        }
        const float* pbB = pair_bias
            + ((size_t)((b * HH + h) * QL + q0)) * KLEN + kt * 64;
        #pragma unroll
        for (int p = 0; p < 4; p++) {   // bias: 64x64f = 1024 chunks, 4/thread
            int ch = tid + p * 256;
            int r = ch >> 4, c = (ch & 15) * 4;
            cp16(bsm + (st * 64 + r) * 76 + c, pbB + (size_t)r * KLEN + c);
        }
    };

    // Prologue: Q + mask + tile 0
    {
        int r = tid >> 2, c = (tid & 3) * 8;
        cp16(qs + r * 40 + c, g_qp + (size_t)(b * QL + q0 + r) * CC + h * DD + c);
    }
    cp16(msk + tid * 4, mask_bias + (size_t)b * KLEN + tid * 4);
    loadKVB(0, 0);
    CP_COMMIT();
    CP_WAIT0();
    __syncthreads();

    unsigned aq[2][4];
    #pragma unroll
    for (int kst = 0; kst < 2; kst++) {
        aq[kst][0] = *(const unsigned*)(qs + (wr + g    ) * 40 + kst * 16 + 2 * tig);
        aq[kst][1] = *(const unsigned*)(qs + (wr + g + 8) * 40 + kst * 16 + 2 * tig);
        aq[kst][2] = *(const unsigned*)(qs + (wr + g    ) * 40 + kst * 16 + 2 * tig + 8);
        aq[kst][3] = *(const unsigned*)(qs + (wr + g + 8) * 40 + kst * 16 + 2 * tig + 8);
    }

    float o[4][4] = {};        // partial over this warp's key half
    float lsum[4] = {};        // ones-column row sums (fp32, tensor-core)

    for (int kt = 0; kt < 16; kt++) {
        const int k0 = kt * 64;
        const int cur = kt & 1;

        if (kt < 15) {
            loadKVB(cur ^ 1, kt + 1);
            CP_COMMIT();
        }

        // QK^T over 32 keys (4 n-tiles)
        const __half* kb = ks + cur * 64 * 40;
        float s[4][4] = {};
        #pragma unroll
        for (int kst = 0; kst < 2; kst++) {
            #pragma unroll
            for (int nt = 0; nt < 4; nt++) {
                int krow = koff + nt * 8 + g;
                unsigned b0 = *(const unsigned*)(kb + krow * 40 + kst * 16 + 2 * tig);
                unsigned b1 = *(const unsigned*)(kb + krow * 40 + kst * 16 + 2 * tig + 8);
                mma_f16(s[nt], aq[kst][0], aq[kst][1], aq[kst][2], aq[kst][3], b0, b1);
            }
        }

        // bias (x log2e) in fp32, pack, clamp, f16x2 exp2
        const float* bb = bsm + cur * 64 * 76;
        unsigned ph[4][2];
        #pragma unroll
        for (int nt = 0; nt < 4; nt++) {
            int col = koff + nt * 8 + 2 * tig;
            float2 mk = *(const float2*)(msk + k0 + col);
            float2 p0 = *(const float2*)(bb + (wr + g    ) * 76 + col);
            float2 p1 = *(const float2*)(bb + (wr + g + 8) * 76 + col);
            float t0 = fmaf(p0.x + mk.x, L2E, s[nt][0]);
            float t1 = fmaf(p0.y + mk.y, L2E, s[nt][1]);
            float t2 = fmaf(p1.x + mk.x, L2E, s[nt][2]);
            float t3 = fmaf(p1.y + mk.y, L2E, s[nt][3]);
            ph[nt][0] = ex2h2(hmin2c(packh2(t0, t1), CLMP));
            ph[nt][1] = ex2h2(hmin2c(packh2(t2, t3), CLMP));
        }

        // AV over 32 keys (2 k-steps) + ones-column row-sum mma
        const __half* vb = vt + cur * 32 * 72;
        #pragma unroll
        for (int kst = 0; kst < 2; kst++) {
            unsigned a0 = ph[2 * kst    ][0];
            unsigned a1 = ph[2 * kst    ][1];
            unsigned a2 = ph[2 * kst + 1][0];
            unsigned a3 = ph[2 * kst + 1][1];
            mma_f16(lsum, a0, a1, a2, a3, bone, bone);
            #pragma unroll
            for (int nt = 0; nt < 4; nt++) {
                unsigned b0 = *(const unsigned*)(vb + (nt * 8 + g) * 72 + koff + kst * 16 + 2 * tig);
                unsigned b1 = *(const unsigned*)(vb + (nt * 8 + g) * 72 + koff + kst * 16 + 2 * tig + 8);
                mma_f16(o[nt], a0, a1, a2, a3, b0, b1);
            }
        }

        if (kt < 15) { CP_WAIT0(); }
        __syncthreads();
    }

    // l partials live at tig==0 lanes (column 0); broadcast within quad.
    float l0 = __shfl_sync(0xffffffffu, lsum[0], lane & ~3);
    float l1 = __shfl_sync(0xffffffffu, lsum[2], lane & ~3);

    // Cross-warp reduction: warps 4-7 publish partials, warps 0-3 combine.
    float* osm = (float*)(smc + AT_BS);   // [64][34]
    float* lsm = osm + 64 * 34;           // [64]
    if (warp >= 4) {
        #pragma unroll
        for (int nt = 0; nt < 4; nt++) {
            int col = nt * 8 + 2 * tig;
            *(float2*)&osm[(wr + g    ) * 34 + col] = make_float2(o[nt][0], o[nt][1]);
            *(float2*)&osm[(wr + g + 8) * 34 + col] = make_float2(o[nt][2], o[nt][3]);
        }
        if (tig == 0) {
            lsm[wr + g]     = l0;
            lsm[wr + g + 8] = l1;
        }
    }
    __syncthreads();
    if (warp < 4) {
        float invl0 = 1.0f / (l0 + lsm[wr + g]);
        float invl1 = 1.0f / (l1 + lsm[wr + g + 8]);
        #pragma unroll
        for (int nt = 0; nt < 4; nt++) {
            int col = nt * 8 + 2 * tig;
            float2 q0v = *(const float2*)&osm[(wr + g    ) * 34 + col];
            float2 q1v = *(const float2*)&osm[(wr + g + 8) * 34 + col];
            float v0 = o[nt][0] + q0v.x, v1 = o[nt][1] + q0v.y;
            float v2 = o[nt][2] + q1v.x, v3 = o[nt][3] + q1v.y;
            size_t base0 = (size_t)(b * QL + q0 + wr + g) * CC + h * DD + col;
            size_t base1 = base0 + 8 * (size_t)CC;
            float2 ga = *(const float2*)(g_gp + base0);
            float2 gb = *(const float2*)(g_gp + base1);
            *(__half2*)(g_o + base0) = __floats2half2_rn(v0 * invl0 * ga.x,
                                                         v1 * invl0 * ga.y);
            *(__half2*)(g_o + base1) = __floats2half2_rn(v2 * invl1 * gb.x,
                                                         v3 * invl1 * gb.y);
        }
    }
}

// ---------------------------------------------------------------------------
extern "C" void kernel_launch(void* const* d_in, const int* in_sizes, int n_in,
                              void* d_out, int out_size)
{
    (void)in_sizes; (void)n_in; (void)out_size;
    const float* q_x       = (const float*)d_in[0];
    const float* kv_x      = (const float*)d_in[1];
    const float* mask_bias = (const float*)d_in[2];
    const float* pair_bias = (const float*)d_in[3];
    const float* wq        = (const float*)d_in[4];
    const float* wk        = (const float*)d_in[5];
    const float* wv        = (const float*)d_in[6];
    const float* wg        = (const float*)d_in[7];
    const float* bg        = (const float*)d_in[8];
    const float* wo        = (const float*)d_in[9];
    const float* bo        = (const float*)d_in[10];
    float* out = (float*)d_out;

    static bool attr_done = false;
    if (!attr_done) {
        cudaFuncSetAttribute(gemm_f16, cudaFuncAttributeMaxDynamicSharedMemorySize, GEMM_SMEM);
        cudaFuncSetAttribute(attn_f16, cudaFuncAttributeMaxDynamicSharedMemorySize, ATT_SMEM);
        attr_done = true;
    }

    prep_f16<<<dim3(1024, 3), 256>>>(q_x, kv_x, wq, wk, wv, wg, wo);

    gemm_f16<<<dim3(MM / 64, CC / 64, 4), 256, GEMM_SMEM>>>(bg, bo, nullptr, 0);

    attn_f16<<<dim3(QL / 64, HH, BB), 256, ATT_SMEM>>>(mask_bias, pair_bias);

    gemm_f16<<<dim3(MM / 64, CC / 64, 1), 256, GEMM_SMEM>>>(bg, bo, out, 4);
}

// round 11
// speedup vs baseline: 1.2412x; 1.1707x over previous
#include <cuda_runtime.h>
#include <cuda_fp16.h>
#include <math_constants.h>

#define BB 4
#define QL 1024
#define KLEN 1024
#define CC 256
#define HH 8
#define DD 32
#define MM (BB * QL)

// Scratch device globals (no allocation allowed)
__device__ __half g_xq [MM * CC];      // fp16(q_x)
__device__ __half g_xkv[MM * CC];      // fp16(kv_x)
__device__ __half g_wts[5 * CC * CC];  // fp16(wq,wk,wv,wg,wo)
__device__ __half g_qp[MM * CC];       // fp16(q * log2e / sqrt(D))
__device__ __half g_kp[MM * CC];       // fp16(k)
__device__ __half g_vt[MM * CC];       // fp16(v) TRANSPOSED: [(b*H+h)*D+d][tok]
__device__ float  g_gp[MM * CC];       // sigmoid gate (fp32)
__device__ __half g_o [MM * CC];       // fp16(gated attention out)

__device__ __forceinline__ unsigned packh2(float lo, float hi) {
    __half2 h = __floats2half2_rn(lo, hi);
    return *reinterpret_cast<unsigned*>(&h);
}
__device__ __forceinline__ unsigned ex2h2(unsigned x) {
    unsigned d;
    asm("ex2.approx.f16x2 %0, %1;" : "=r"(d) : "r"(x));
    return d;
}
__device__ __forceinline__ unsigned hmin2c(unsigned a, unsigned b) {
    unsigned d;
    asm("min.f16x2 %0, %1, %2;" : "=r"(d) : "r"(a), "r"(b));
    return d;
}

__device__ __forceinline__ void mma_f16(float c[4],
                                        unsigned a0, unsigned a1, unsigned a2, unsigned a3,
                                        unsigned b0, unsigned b1) {
    asm volatile(
        "mma.sync.aligned.m16n8k16.row.col.f32.f16.f16.f32 "
        "{%0,%1,%2,%3}, {%4,%5,%6,%7}, {%8,%9}, {%0,%1,%2,%3};"
        : "+f"(c[0]), "+f"(c[1]), "+f"(c[2]), "+f"(c[3])
        : "r"(a0), "r"(a1), "r"(a2), "r"(a3), "r"(b0), "r"(b1));
}

__device__ __forceinline__ void cp16(void* dst_smem, const void* src) {
    unsigned d = (unsigned)__cvta_generic_to_shared(dst_smem);
    asm volatile("cp.async.cg.shared.global [%0], [%1], 16;" :: "r"(d), "l"(src));
}
#define CP_COMMIT() asm volatile("cp.async.commit_group;")
#define CP_WAIT0()  asm volatile("cp.async.wait_group 0;")
#define CP_WAIT1()  asm volatile("cp.async.wait_group 1;")
#define CP_WAIT2()  asm volatile("cp.async.wait_group 2;")

// ---------------------------------------------------------------------------
// Prep: fp16-convert q_x, kv_x, five weight matrices. Grid (1024,3) x 256.
// ---------------------------------------------------------------------------
__global__ __launch_bounds__(256)
void prep_f16(const float* __restrict__ qx, const float* __restrict__ kvx,
              const float* __restrict__ wq, const float* __restrict__ wk,
              const float* __restrict__ wv, const float* __restrict__ wg,
              const float* __restrict__ wo)
{
    const int seg = blockIdx.y;
    const int i4 = blockIdx.x * 256 + threadIdx.x;
    const float* src; __half* dst; int idx = i4;
    if (seg == 0)      { src = qx;  dst = g_xq;  }
    else if (seg == 1) { src = kvx; dst = g_xkv; }
    else {
        if (i4 >= 5 * CC * CC / 4) return;
        int w = i4 / (CC * CC / 4);
        idx = i4 - w * (CC * CC / 4);
        const float* ws[5] = {wq, wk, wv, wg, wo};
        src = ws[w];
        dst = g_wts + (size_t)w * CC * CC;
    }
    float4 v = ((const float4*)src)[idx];
    uint2 u;
    u.x = packh2(v.x, v.y);
    u.y = packh2(v.z, v.w);
    ((uint2*)dst)[idx] = u;
}

// ---------------------------------------------------------------------------
// fp16 GEMM (R5/R7 proven config): Y[m][n]=sum_k X[m][k]*W[n][k].
// BM=64 BN=64 BK=32; 256 thr (2m x 4n warps). 3-stage cp.async pipeline.
// modes: 0 q(*log2e/sqrtD) 1 k 2 v(transposed out) 3 gate 4 out.
// ---------------------------------------------------------------------------
#define G_STAGE (64 * 40)
#define GEMM_SMEM (3 * 2 * G_STAGE * 2)         // 30720 B

__global__ __launch_bounds__(256)
void gemm_f16(const float* __restrict__ bg, const float* __restrict__ bo,
              float* __restrict__ outp, int mode_base)
{
    extern __shared__ __half smh[];
    __half* As = smh;                  // [3][64][40]
    __half* Bs = smh + 3 * G_STAGE;    // [3][64][40]

    const int mode = mode_base + blockIdx.z;
    const __half* X; const __half* W; const float* bias = nullptr;
    switch (mode) {
        case 0:  X = g_xq;  W = g_wts;               break;
        case 1:  X = g_xkv; W = g_wts + 1 * CC * CC; break;
        case 2:  X = g_xkv; W = g_wts + 2 * CC * CC; break;
        case 3:  X = g_xq;  W = g_wts + 3 * CC * CC; bias = bg; break;
        default: X = g_o;   W = g_wts + 4 * CC * CC; bias = bo; break;
    }

    const int tid  = threadIdx.x;
    const int lane = tid & 31;
    const int warp = tid >> 5;
    const int wm = warp & 1;
    const int wn = warp >> 1;
    const int g = lane >> 2, tig = lane & 3;
    const int m0 = blockIdx.x * 64;
    const int n0 = blockIdx.y * 64;

    const int r = tid >> 2;            // 0..63
    const int c = (tid & 3) * 8;       // 0..24

    auto loadTiles = [&](int st, int kk) {
        cp16(As + (st * 64 + r) * 40 + c, X + (size_t)(m0 + r) * CC + kk + c);
        cp16(Bs + (st * 64 + r) * 40 + c, W + (size_t)(n0 + r) * CC + kk + c);
    };

    float acc[2][2][4] = {};

    loadTiles(0, 0);  CP_COMMIT();
    loadTiles(1, 32); CP_COMMIT();

    for (int kt = 0; kt < 8; kt++) {
        const int st = kt % 3;
        if (kt + 2 < 8) {
            loadTiles((kt + 2) % 3, (kt + 2) * 32);
            CP_COMMIT();
            CP_WAIT2();
        } else if (kt == 6) {
            CP_WAIT1();
        } else {
            CP_WAIT0();
        }
        __syncthreads();

        const __half* Ab = As + st * G_STAGE;
        const __half* Bb = Bs + st * G_STAGE;
        #pragma unroll
        for (int kst = 0; kst < 2; kst++) {
            unsigned a[2][4];
            #pragma unroll
            for (int mt = 0; mt < 2; mt++) {
                int row = wm * 32 + mt * 16;
                a[mt][0] = *(const unsigned*)(Ab + (row + g    ) * 40 + kst * 16 + 2 * tig);
                a[mt][1] = *(const unsigned*)(Ab + (row + g + 8) * 40 + kst * 16 + 2 * tig);
                a[mt][2] = *(const unsigned*)(Ab + (row + g    ) * 40 + kst * 16 + 2 * tig + 8);
                a[mt][3] = *(const unsigned*)(Ab + (row + g + 8) * 40 + kst * 16 + 2 * tig + 8);
            }
            #pragma unroll
            for (int nt = 0; nt < 2; nt++) {
                int n = wn * 16 + nt * 8;
                unsigned b0 = *(const unsigned*)(Bb + (n + g) * 40 + kst * 16 + 2 * tig);
                unsigned b1 = *(const unsigned*)(Bb + (n + g) * 40 + kst * 16 + 2 * tig + 8);
                mma_f16(acc[0][nt], a[0][0], a[0][1], a[0][2], a[0][3], b0, b1);
                mma_f16(acc[1][nt], a[1][0], a[1][1], a[1][2], a[1][3], b0, b1);
            }
        }
        __syncthreads();
    }

    // Epilogue
    #pragma unroll
    for (int mt = 0; mt < 2; mt++) {
        int row0 = m0 + wm * 32 + mt * 16 + g;
        #pragma unroll
        for (int nt = 0; nt < 2; nt++) {
            int col = n0 + wn * 16 + nt * 8 + 2 * tig;
            float v[4] = {acc[mt][nt][0], acc[mt][nt][1], acc[mt][nt][2], acc[mt][nt][3]};
            if (mode == 0) {
                const float QS = 1.4426950408889634f / 5.656854249492381f;
                #pragma unroll
                for (int u = 0; u < 4; u++) v[u] *= QS;
            } else if (mode == 3) {
                float b0v = bias[col], b1v = bias[col + 1];
                v[0] = 1.0f / (1.0f + __expf(-(v[0] + b0v)));
                v[1] = 1.0f / (1.0f + __expf(-(v[1] + b1v)));
                v[2] = 1.0f / (1.0f + __expf(-(v[2] + b0v)));
                v[3] = 1.0f / (1.0f + __expf(-(v[3] + b1v)));
            } else if (mode == 4) {
                float b0v = bias[col], b1v = bias[col + 1];
                v[0] += b0v; v[1] += b1v; v[2] += b0v; v[3] += b1v;
            }
            if (mode == 2) {
                int bidx = row0 >> 10, tok = row0 & 1023;
                int hh = col >> 5, dd = col & 31;
                size_t base = ((size_t)(bidx * HH + hh) * DD + dd) * KLEN + tok;
                g_vt[base]            = __float2half_rn(v[0]);
                g_vt[base + KLEN]     = __float2half_rn(v[1]);
                g_vt[base + 8]        = __float2half_rn(v[2]);
                g_vt[base + KLEN + 8] = __float2half_rn(v[3]);
            } else if (mode == 0 || mode == 1) {
                __half* Y = (mode == 0) ? g_qp : g_kp;
                *(__half2*)(Y + (size_t)row0 * CC + col)       = __floats2half2_rn(v[0], v[1]);
                *(__half2*)(Y + (size_t)(row0 + 8) * CC + col) = __floats2half2_rn(v[2], v[3]);
            } else if (mode == 3) {
                *(float2*)(g_gp + (size_t)row0 * CC + col)       = make_float2(v[0], v[1]);
                *(float2*)(g_gp + (size_t)(row0 + 8) * CC + col) = make_float2(v[2], v[3]);
            } else {
                *(float2*)(outp + (size_t)row0 * CC + col)       = make_float2(v[0], v[1]);
                *(float2*)(outp + (size_t)(row0 + 8) * CC + col) = make_float2(v[2], v[3]);
            }
        }
    }
}

// ---------------------------------------------------------------------------
// Fused flash attention + gating v6:
// R10 numerics (f16x2 exp, ones-column lsum mma) but smem cut to 55 KB:
//  - qs aliased into bias stage 1 (consumed to regs before stage 1 written)
//  - mask via direct LDG (L2-resident, 16 KB)
//  - bias stride 72 (half-warp bank-disjoint for LDS.64)
// -> 4 CTAs/SM, grid 512 fully resident in ONE wave (592 slots).
// Grid (Q/64, H, B), 256 threads, key-split 8 warps.
// ---------------------------------------------------------------------------
#define AT_KS   0
#define AT_VT   10240
#define AT_BS   19456
#define AT_QS   (AT_BS + 64 * 72 * 4)     // alias: inside bias stage 1
#define ATT_SMEM (AT_BS + 2 * 64 * 72 * 4)   // 56320 B

__global__ __launch_bounds__(256, 4)
void attn_f16(const float* __restrict__ mask_bias,
              const float* __restrict__ pair_bias)
{
    extern __shared__ char smc[];
    __half* ks  = (__half*)(smc + AT_KS);    // [2][64][40]
    __half* vt  = (__half*)(smc + AT_VT);    // [2][32][72]
    float*  bsm = (float*)(smc + AT_BS);     // [2][64][72]
    __half* qs  = (__half*)(smc + AT_QS);    // [64][40] (aliases bias stage 1)

    const int tid  = threadIdx.x;
    const int lane = tid & 31;
    const int warp = tid >> 5;
    const int g = lane >> 2, tig = lane & 3;
    const int q0 = blockIdx.x * 64;
    const int h  = blockIdx.y;
    const int b  = blockIdx.z;
    const int wr   = (warp & 3) * 16;    // query-row offset
    const int koff = (warp >> 2) * 32;   // key offset within tile
    const float L2E = 1.4426950408889634f;
    const unsigned bone = (lane < 4) ? 0x3C003C00u : 0u;  // ones column (n=0)
    const unsigned CLMP = 0x4BF84BF8u;                    // (15.9375, 15.9375)

    auto loadKVB = [&](int st, int kt) {
        {   // K: 64x32h = 256 chunks, 1/thread
            int r = tid >> 2, c = (tid & 3) * 8;
            cp16(ks + (st * 64 + r) * 40 + c,
                 g_kp + (size_t)(b * KLEN + kt * 64 + r) * CC + h * DD + c);
        }
        {   // Vt: 32x64h = 256 chunks, 1/thread
            int r = tid >> 3, c = (tid & 7) * 8;
            cp16(vt + (st * 32 + r) * 72 + c,
                 g_vt + ((size_t)(b * HH + h) * DD + r) * KLEN + kt * 64 + c);
        }
        const float* pbB = pair_bias
            + ((size_t)((b * HH + h) * QL + q0)) * KLEN + kt * 64;
        #pragma unroll
        for (int p = 0; p < 4; p++) {   // bias: 64x64f = 1024 chunks, 4/thread
            int ch = tid + p * 256;
            int r = ch >> 4, c = (ch & 15) * 4;
            cp16(bsm + (st * 64 + r) * 72 + c, pbB + (size_t)r * KLEN + c);
        }
    };

    // Prologue: Q (into aliased region) + K/V/bias tile 0
    {
        int r = tid >> 2, c = (tid & 3) * 8;
        cp16(qs + r * 40 + c, g_qp + (size_t)(b * QL + q0 + r) * CC + h * DD + c);
    }
    loadKVB(0, 0);
    CP_COMMIT();
    CP_WAIT0();
    __syncthreads();

    // Consume Q into registers BEFORE bias stage 1 (same bytes) is written.
    unsigned aq[2][4];
    #pragma unroll
    for (int kst = 0; kst < 2; kst++) {
        aq[kst][0] = *(const unsigned*)(qs + (wr + g    ) * 40 + kst * 16 + 2 * tig);
        aq[kst][1] = *(const unsigned*)(qs + (wr + g + 8) * 40 + kst * 16 + 2 * tig);
        aq[kst][2] = *(const unsigned*)(qs + (wr + g    ) * 40 + kst * 16 + 2 * tig + 8);
        aq[kst][3] = *(const unsigned*)(qs + (wr + g + 8) * 40 + kst * 16 + 2 * tig + 8);
    }
    __syncthreads();   // all warps done reading qs before stage-1 prefetch

    float o[4][4] = {};        // partial over this warp's key half
    float lsum[4] = {};        // ones-column row sums (fp32, tensor-core)

    for (int kt = 0; kt < 16; kt++) {
        const int k0 = kt * 64;
        const int cur = kt & 1;

        if (kt < 15) {
            loadKVB(cur ^ 1, kt + 1);
            CP_COMMIT();
        }

        // mask via direct LDG (L2-resident), hoisted before QK mma
        float2 mk[4];
        #pragma unroll
        for (int nt = 0; nt < 4; nt++)
            mk[nt] = *(const float2*)(mask_bias + (size_t)b * KLEN + k0 + koff + nt * 8 + 2 * tig);

        // QK^T over 32 keys (4 n-tiles)
        const __half* kb = ks + cur * 64 * 40;
        float s[4][4] = {};
        #pragma unroll
        for (int kst = 0; kst < 2; kst++) {
            #pragma unroll
            for (int nt = 0; nt < 4; nt++) {
                int krow = koff + nt * 8 + g;
                unsigned b0 = *(const unsigned*)(kb + krow * 40 + kst * 16 + 2 * tig);
                unsigned b1 = *(const unsigned*)(kb + krow * 40 + kst * 16 + 2 * tig + 8);
                mma_f16(s[nt], aq[kst][0], aq[kst][1], aq[kst][2], aq[kst][3], b0, b1);
            }
        }

        // bias (x log2e) in fp32, pack, clamp, f16x2 exp2
        const float* bb = bsm + cur * 64 * 72;
        unsigned ph[4][2];
        #pragma unroll
        for (int nt = 0; nt < 4; nt++) {
            int col = koff + nt * 8 + 2 * tig;
            float2 p0 = *(const float2*)(bb + (wr + g    ) * 72 + col);
            float2 p1 = *(const float2*)(bb + (wr + g + 8) * 72 + col);
            float t0 = fmaf(p0.x + mk[nt].x, L2E, s[nt][0]);
            float t1 = fmaf(p0.y + mk[nt].y, L2E, s[nt][1]);
            float t2 = fmaf(p1.x + mk[nt].x, L2E, s[nt][2]);
            float t3 = fmaf(p1.y + mk[nt].y, L2E, s[nt][3]);
            ph[nt][0] = ex2h2(hmin2c(packh2(t0, t1), CLMP));
            ph[nt][1] = ex2h2(hmin2c(packh2(t2, t3), CLMP));
        }

        // AV over 32 keys (2 k-steps) + ones-column row-sum mma
        const __half* vb = vt + cur * 32 * 72;
        #pragma unroll
        for (int kst = 0; kst < 2; kst++) {
            unsigned a0 = ph[2 * kst    ][0];
            unsigned a1 = ph[2 * kst    ][1];
            unsigned a2 = ph[2 * kst + 1][0];
            unsigned a3 = ph[2 * kst + 1][1];
            mma_f16(lsum, a0, a1, a2, a3, bone, bone);
            #pragma unroll
            for (int nt = 0; nt < 4; nt++) {
                unsigned b0 = *(const unsigned*)(vb + (nt * 8 + g) * 72 + koff + kst * 16 + 2 * tig);
                unsigned b1 = *(const unsigned*)(vb + (nt * 8 + g) * 72 + koff + kst * 16 + 2 * tig + 8);
                mma_f16(o[nt], a0, a1, a2, a3, b0, b1);
            }
        }

        if (kt < 15) { CP_WAIT0(); }
        __syncthreads();
    }

    // l partials live at tig==0 lanes (column 0); broadcast within quad.
    float l0 = __shfl_sync(0xffffffffu, lsum[0], lane & ~3);
    float l1 = __shfl_sync(0xffffffffu, lsum[2], lane & ~3);

    // Cross-warp reduction: warps 4-7 publish partials, warps 0-3 combine.
    float* osm = (float*)(smc + AT_BS);   // [64][34]
    float* lsm = osm + 64 * 34;           // [64]
    if (warp >= 4) {
        #pragma unroll
        for (int nt = 0; nt < 4; nt++) {
            int col = nt * 8 + 2 * tig;
            *(float2*)&osm[(wr + g    ) * 34 + col] = make_float2(o[nt][0], o[nt][1]);
            *(float2*)&osm[(wr + g + 8) * 34 + col] = make_float2(o[nt][2], o[nt][3]);
        }
        if (tig == 0) {
            lsm[wr + g]     = l0;
            lsm[wr + g + 8] = l1;
        }
    }
    __syncthreads();
    if (warp < 4) {
        float invl0 = 1.0f / (l0 + lsm[wr + g]);
        float invl1 = 1.0f / (l1 + lsm[wr + g + 8]);
        #pragma unroll
        for (int nt = 0; nt < 4; nt++) {
            int col = nt * 8 + 2 * tig;
            float2 q0v = *(const float2*)&osm[(wr + g    ) * 34 + col];
            float2 q1v = *(const float2*)&osm[(wr + g + 8) * 34 + col];
            float v0 = o[nt][0] + q0v.x, v1 = o[nt][1] + q0v.y;
            float v2 = o[nt][2] + q1v.x, v3 = o[nt][3] + q1v.y;
            size_t base0 = (size_t)(b * QL + q0 + wr + g) * CC + h * DD + col;
            size_t base1 = base0 + 8 * (size_t)CC;
            float2 ga = *(const float2*)(g_gp + base0);
            float2 gb = *(const float2*)(g_gp + base1);
            *(__half2*)(g_o + base0) = __floats2half2_rn(v0 * invl0 * ga.x,
                                                         v1 * invl0 * ga.y);
            *(__half2*)(g_o + base1) = __floats2half2_rn(v2 * invl1 * gb.x,
                                                         v3 * invl1 * gb.y);
        }
    }
}

// ---------------------------------------------------------------------------
extern "C" void kernel_launch(void* const* d_in, const int* in_sizes, int n_in,
                              void* d_out, int out_size)
{
    (void)in_sizes; (void)n_in; (void)out_size;
    const float* q_x       = (const float*)d_in[0];
    const float* kv_x      = (const float*)d_in[1];
    const float* mask_bias = (const float*)d_in[2];
    const float* pair_bias = (const float*)d_in[3];
    const float* wq        = (const float*)d_in[4];
    const float* wk        = (const float*)d_in[5];
    const float* wv        = (const float*)d_in[6];
    const float* wg        = (const float*)d_in[7];
    const float* bg        = (const float*)d_in[8];
    const float* wo        = (const float*)d_in[9];
    const float* bo        = (const float*)d_in[10];
    float* out = (float*)d_out;

    static bool attr_done = false;
    if (!attr_done) {
        cudaFuncSetAttribute(gemm_f16, cudaFuncAttributeMaxDynamicSharedMemorySize, GEMM_SMEM);
        cudaFuncSetAttribute(attn_f16, cudaFuncAttributeMaxDynamicSharedMemorySize, ATT_SMEM);
        attr_done = true;
    }

    prep_f16<<<dim3(1024, 3), 256>>>(q_x, kv_x, wq, wk, wv, wg, wo);

    gemm_f16<<<dim3(MM / 64, CC / 64, 4), 256, GEMM_SMEM>>>(bg, bo, nullptr, 0);

    attn_f16<<<dim3(QL / 64, HH, BB), 256, ATT_SMEM>>>(mask_bias, pair_bias);

    gemm_f16<<<dim3(MM / 64, CC / 64, 1), 256, GEMM_SMEM>>>(bg, bo, out, 4);
}